// round 9
// baseline (speedup 1.0000x reference)
#include <cuda_runtime.h>
#include <cstdint>

#define N0 4096
#define N1 8192
#define N2 4096
#define NBLK 296           // 2 CTAs per SM
#define BLK 512

// Scratch (allocation-free: __device__ global)
__device__ __align__(16) float g_x1[N1];

__device__ __forceinline__ float warp_sum(float v) {
#pragma unroll
    for (int o = 16; o > 0; o >>= 1) v += __shfl_xor_sync(0xffffffffu, v, o);
    return v;
}

__device__ __forceinline__ uint32_t smem_u32(const void* p) {
    return (uint32_t)__cvta_generic_to_shared(p);
}
__device__ __forceinline__ uint64_t evict_first_policy() {
    uint64_t pol;
    asm("createpolicy.fractional.L2::evict_first.b64 %0, 1.0;" : "=l"(pol));
    return pol;
}
__device__ __forceinline__ void cp_async16_ef(uint32_t dst, const void* src, uint64_t pol) {
    asm volatile("cp.async.cg.shared.global.L2::cache_hint [%0], [%1], 16, %2;"
                 :: "r"(dst), "l"(src), "l"(pol));
}
__device__ __forceinline__ void l2_prefetch_bulk(const void* src, uint32_t bytes) {
    asm volatile("cp.async.bulk.prefetch.L2.global [%0], %1;" :: "l"(src), "r"(bytes));
}
#define CP_COMMIT() asm volatile("cp.async.commit_group;" ::: "memory")
#define CP_WAIT(n)  asm volatile("cp.async.wait_group %0;" :: "n"(n) : "memory")

// Block-wide reduction of 8 partial sums (512 threads / 16 warps). Deterministic.
__device__ __forceinline__ void block_reduce8(float s[8], float (*sh)[16], float* s_sums)
{
    int tid = threadIdx.x;
    int w = tid >> 5, l = tid & 31;
#pragma unroll
    for (int k = 0; k < 8; k++) s[k] = warp_sum(s[k]);
    if (l == 0) {
#pragma unroll
        for (int k = 0; k < 8; k++) sh[k][w] = s[k];
    }
    __syncthreads();
    if (tid < 256) {
        int k = tid >> 5, ln = tid & 31;
        float v = (ln < 16) ? sh[k][ln] : 0.f;
        v = warp_sum(v);
        if (ln == 0) s_sums[k] = v;
    }
}

__device__ __forceinline__ float heb_row_val(
    int row,
    const float* __restrict__ act_post,
    const float* __restrict__ b_post,
    const float* __restrict__ c_post,
    const float* __restrict__ d_post,
    const float* __restrict__ e_post,
    const float* __restrict__ sums)
{
    float P = b_post[row] * act_post[row];
    float C = c_post[row] * act_post[row];
    float D = d_post[row];
    float E = e_post[row];
    return 0.5f * (sums[0] + P * sums[1] + C * sums[2] + D * sums[3]
          + E * (sums[4] + P * sums[5] + C * sums[6] + D * sums[7]));
}

__device__ __forceinline__ void heb_partial4(
    float s[8], float4 xv, float4 actv, float4 av, float4 cv, float4 dv, float4 ev)
{
    float xs[4]  = {xv.x, xv.y, xv.z, xv.w};
    float acs[4] = {actv.x, actv.y, actv.z, actv.w};
    float as[4]  = {av.x, av.y, av.z, av.w};
    float cs[4]  = {cv.x, cv.y, cv.z, cv.w};
    float ds[4]  = {dv.x, dv.y, dv.z, dv.w};
    float es[4]  = {ev.x, ev.y, ev.z, ev.w};
#pragma unroll
    for (int j = 0; j < 4; j++) {
        float x = xs[j], e = es[j];
        float p = as[j] * acs[j];
        float c = cs[j] * acs[j];
        float d = ds[j];
        s[0] += e * p * x;  s[1] += e * x;
        s[2] += e * c * x;  s[3] += e * d * x;
        s[4] += p * x;      s[5] += x;
        s[6] += c * x;      s[7] += d * x;
    }
}

// ---------------------------------------------------------------------------
// Fused GEMV: cp.async row pipeline NBUF deep, x in registers, thread t owns
// f4-columns {t, t+512, ...}. Per-row shfl reduce; no block barrier on the
// data path. Optionally prefetches PF rows (32 KB each) of PFBASE into L2,
// one per mainloop row (warp 0 lane 0).
// ---------------------------------------------------------------------------
template <int NCOL4, int NROWS_OUT, bool TANH_IN, bool TANH_OUT, int NBUF, bool PF>
__device__ __forceinline__ void gemv_fused(
    const float* __restrict__ W,
    const float* __restrict__ xin_src,
    const float* __restrict__ act_pre,
    const float* __restrict__ a_pre,
    const float* __restrict__ c_pre,
    const float* __restrict__ d_pre,
    const float* __restrict__ e_pre,
    const float* __restrict__ act_post,
    const float* __restrict__ b_post,
    const float* __restrict__ c_post,
    const float* __restrict__ d_post,
    const float* __restrict__ e_post,
    float* __restrict__ out,
    const float* __restrict__ pf_base,   // W1 (only if PF)
    int pf_lo, int pf_cnt)               // W1 row range to prefetch
{
    constexpr int F4PT = NCOL4 / BLK;     // float4 per thread per row (2 or 4)

    extern __shared__ float4 dynbuf[];    // NBUF * NCOL4 float4 (96 KB)
    __shared__ float sh[8][16];
    __shared__ float s_sums[8];
    __shared__ float s_heb[32];
    __shared__ float s_part[2][8][16];

    int tid = threadIdx.x;
    int lane = tid & 31;
    int warp = tid >> 5;

    uint64_t pol = evict_first_policy();

    int r_lo = (int)(((long long)blockIdx.x * NROWS_OUT) / NBLK);
    int r_hi = (int)(((long long)(blockIdx.x + 1) * NROWS_OUT) / NBLK);
    int nrows = r_hi - r_lo;

    const float4* Wb = reinterpret_cast<const float4*>(W) + (size_t)r_lo * NCOL4;
    uint32_t sbase = smem_u32(dynbuf);

    // Kick off DRAM immediately: prefetch first NBUF rows.
#pragma unroll
    for (int r = 0; r < NBUF; r++) {
        if (r < nrows) {
#pragma unroll
            for (int j = 0; j < F4PT; j++) {
                int col = tid + j * BLK;
                cp_async16_ef(sbase + (uint32_t)(r * NCOL4 + col) * 16u,
                              Wb + (size_t)r * NCOL4 + col, pol);
            }
        }
        CP_COMMIT();
    }

    // x into registers (+tanh), Hebbian pre-side sums (overlaps prefetch).
    float4 xr[F4PT];
    {
        float s[8] = {0.f, 0.f, 0.f, 0.f, 0.f, 0.f, 0.f, 0.f};
#pragma unroll
        for (int j = 0; j < F4PT; j++) {
            int i = tid + j * BLK;
            float4 xv = reinterpret_cast<const float4*>(xin_src)[i];
            if (TANH_IN)
                xv = make_float4(tanhf(xv.x), tanhf(xv.y), tanhf(xv.z), tanhf(xv.w));
            xr[j] = xv;
            float4 actv = reinterpret_cast<const float4*>(act_pre)[i];
            float4 av   = reinterpret_cast<const float4*>(a_pre)[i];
            float4 cv   = reinterpret_cast<const float4*>(c_pre)[i];
            float4 dv   = reinterpret_cast<const float4*>(d_pre)[i];
            float4 ev   = reinterpret_cast<const float4*>(e_pre)[i];
            heb_partial4(s, xv, actv, av, cv, dv, ev);
        }
        block_reduce8(s, sh, s_sums);
    }
    __syncthreads();
    if (tid < nrows) {
        s_heb[tid] = heb_row_val(r_lo + tid, act_post, b_post, c_post, d_post,
                                 e_post, s_sums);
    }
    __syncthreads();

    // Rolling state.
    int rdSlot = 0;
    int wrSlot = 0;                               // row NBUF writes slot 0
    const float4* gsrc = Wb + (size_t)NBUF * NCOL4 + tid;

    int par = 0;
    for (int r = 0; r < nrows; r++) {
        CP_WAIT(NBUF - 1);

        // L2 prefetch of W1 for the next layer: 1 row (32 KB) per iteration.
        if (PF && warp == 0 && lane == 0 && r < pf_cnt) {
            l2_prefetch_bulk(pf_base + (size_t)(pf_lo + r) * N1, N1 * 4u);
        }

        const float4* buf = dynbuf + (size_t)rdSlot * NCOL4;
        float4 wv[F4PT];
#pragma unroll
        for (int j = 0; j < F4PT; j++) wv[j] = buf[tid + j * BLK];
        rdSlot = (rdSlot + 1 == NBUF) ? 0 : rdSlot + 1;

        float acc = 0.f;
#pragma unroll
        for (int j = 0; j < F4PT; j++) {
            acc = fmaf(wv[j].x, xr[j].x, acc);
            acc = fmaf(wv[j].y, xr[j].y, acc);
            acc = fmaf(wv[j].z, xr[j].z, acc);
            acc = fmaf(wv[j].w, xr[j].w, acc);
        }
        float p = warp_sum(acc);
        if (lane == 0) s_part[par][r & 7][warp] = p;

        // Refill ring slot (row r+NBUF); empty commit keeps group cadence.
        if (r + NBUF < nrows) {
            uint32_t wbase = sbase + (uint32_t)(wrSlot * NCOL4 + tid) * 16u;
#pragma unroll
            for (int j = 0; j < F4PT; j++)
                cp_async16_ef(wbase + (uint32_t)(j * BLK) * 16u, gsrc + j * BLK, pol);
        }
        wrSlot = (wrSlot + 1 == NBUF) ? 0 : wrSlot + 1;
        gsrc += NCOL4;
        CP_COMMIT();

        if ((r & 7) == 7 || r == nrows - 1) {
            __syncthreads();
            if (tid < 256) {
                int rr = (r & ~7) + warp;     // warp = 0..7 here
                if (rr < nrows) {
                    float v = (lane < 16) ? s_part[par][warp][lane] : 0.f;
                    v = warp_sum(v);
                    if (lane == 0) {
                        float y = v + s_heb[rr];
                        out[r_lo + rr] = TANH_OUT ? tanhf(y) : y;
                    }
                }
            }
            par ^= 1;
        }
    }
}

// ---------------------------------------------------------------------------
__global__ void __launch_bounds__(BLK, 2) k_gemv0(
    const float* __restrict__ W0,
    const float* __restrict__ inputs,
    const float* __restrict__ act0,
    const float* __restrict__ a0,
    const float* __restrict__ c0,
    const float* __restrict__ d0,
    const float* __restrict__ e0,
    const float* __restrict__ act1,
    const float* __restrict__ b1,
    const float* __restrict__ c1,
    const float* __restrict__ d1,
    const float* __restrict__ e1,
    const float* __restrict__ W1)
{
    // W1 rows this block's gemv1 twin will read:
    int pf_lo = (int)(((long long)blockIdx.x * N2) / NBLK);
    int pf_hi = (int)(((long long)(blockIdx.x + 1) * N2) / NBLK);
    gemv_fused<N0 / 4, N1, true, true, 6, true>(
        W0, inputs, act0, a0, c0, d0, e0,
        act1, b1, c1, d1, e1, g_x1,
        W1, pf_lo, pf_hi - pf_lo);
}

__global__ void __launch_bounds__(BLK, 2) k_gemv1(
    const float* __restrict__ W1,
    const float* __restrict__ act1,
    const float* __restrict__ a1,
    const float* __restrict__ c1,
    const float* __restrict__ d1,
    const float* __restrict__ e1,
    const float* __restrict__ act2,
    const float* __restrict__ b2,
    const float* __restrict__ c2,
    const float* __restrict__ d2,
    const float* __restrict__ e2,
    float* __restrict__ out)
{
    gemv_fused<N1 / 4, N2, false, false, 3, false>(
        W1, g_x1, act1, a1, c1, d1, e1,
        act2, b2, c2, d2, e2, out,
        nullptr, 0, 0);
}

// ---------------------------------------------------------------------------
extern "C" void kernel_launch(void* const* d_in, const int* in_sizes, int n_in,
                              void* d_out, int out_size)
{
    const float* inputs = (const float*)d_in[0];
    const float* act0   = (const float*)d_in[1];
    const float* act1   = (const float*)d_in[2];
    const float* act2   = (const float*)d_in[3];
    const float* W0     = (const float*)d_in[4];
    const float* W1     = (const float*)d_in[5];
    const float* a0     = (const float*)d_in[6];
    const float* c0     = (const float*)d_in[7];
    const float* d0     = (const float*)d_in[8];
    const float* e0     = (const float*)d_in[9];
    const float* a1     = (const float*)d_in[10];
    const float* b1     = (const float*)d_in[11];
    const float* c1     = (const float*)d_in[12];
    const float* d1     = (const float*)d_in[13];
    const float* e1     = (const float*)d_in[14];
    const float* b2     = (const float*)d_in[15];
    const float* c2     = (const float*)d_in[16];
    const float* d2     = (const float*)d_in[17];
    const float* e2     = (const float*)d_in[18];
    float* out = (float*)d_out;

    // 6 buffers * 1024 f4 (gemv0) == 3 buffers * 2048 f4 (gemv1) == 96 KB.
    const int SMEM_DYN = 6 * (N0 / 4) * (int)sizeof(float4);
    cudaFuncSetAttribute(k_gemv0, cudaFuncAttributeMaxDynamicSharedMemorySize, SMEM_DYN);
    cudaFuncSetAttribute(k_gemv1, cudaFuncAttributeMaxDynamicSharedMemorySize, SMEM_DYN);

    k_gemv0<<<NBLK, BLK, SMEM_DYN>>>(W0, inputs, act0, a0, c0, d0, e0,
                                     act1, b1, c1, d1, e1, W1);
    k_gemv1<<<NBLK, BLK, SMEM_DYN>>>(W1, act1, a1, c1, d1, e1,
                                     act2, b2, c2, d2, e2, out);
}

// round 10
// speedup vs baseline: 1.0678x; 1.0678x over previous
#include <cuda_runtime.h>
#include <cstdint>

#define N0 4096
#define N1 8192
#define N2 4096
#define NBLK 296           // 2 CTAs per SM
#define BLK 512

// Scratch (allocation-free: __device__ global)
__device__ __align__(16) float g_x1[N1];

__device__ __forceinline__ float warp_sum(float v) {
#pragma unroll
    for (int o = 16; o > 0; o >>= 1) v += __shfl_xor_sync(0xffffffffu, v, o);
    return v;
}

__device__ __forceinline__ uint32_t smem_u32(const void* p) {
    return (uint32_t)__cvta_generic_to_shared(p);
}
__device__ __forceinline__ void cp_async16(uint32_t dst, const void* src) {
    asm volatile("cp.async.cg.shared.global [%0], [%1], 16;" :: "r"(dst), "l"(src));
}
#define CP_COMMIT() asm volatile("cp.async.commit_group;" ::: "memory")
#define CP_WAIT(n)  asm volatile("cp.async.wait_group %0;" :: "n"(n) : "memory")

// Block-wide reduction of 8 partial sums (512 threads / 16 warps). Deterministic.
__device__ __forceinline__ void block_reduce8(float s[8], float (*sh)[16], float* s_sums)
{
    int tid = threadIdx.x;
    int w = tid >> 5, l = tid & 31;
#pragma unroll
    for (int k = 0; k < 8; k++) s[k] = warp_sum(s[k]);
    if (l == 0) {
#pragma unroll
        for (int k = 0; k < 8; k++) sh[k][w] = s[k];
    }
    __syncthreads();
    if (tid < 256) {
        int k = tid >> 5, ln = tid & 31;
        float v = (ln < 16) ? sh[k][ln] : 0.f;
        v = warp_sum(v);
        if (ln == 0) s_sums[k] = v;
    }
}

__device__ __forceinline__ float heb_row_val(
    int row,
    const float* __restrict__ act_post,
    const float* __restrict__ b_post,
    const float* __restrict__ c_post,
    const float* __restrict__ d_post,
    const float* __restrict__ e_post,
    const float* __restrict__ sums)
{
    float P = b_post[row] * act_post[row];
    float C = c_post[row] * act_post[row];
    float D = d_post[row];
    float E = e_post[row];
    return 0.5f * (sums[0] + P * sums[1] + C * sums[2] + D * sums[3]
          + E * (sums[4] + P * sums[5] + C * sums[6] + D * sums[7]));
}

__device__ __forceinline__ void heb_partial4(
    float s[8], float4 xv, float4 actv, float4 av, float4 cv, float4 dv, float4 ev)
{
    float xs[4]  = {xv.x, xv.y, xv.z, xv.w};
    float acs[4] = {actv.x, actv.y, actv.z, actv.w};
    float as[4]  = {av.x, av.y, av.z, av.w};
    float cs[4]  = {cv.x, cv.y, cv.z, cv.w};
    float ds[4]  = {dv.x, dv.y, dv.z, dv.w};
    float es[4]  = {ev.x, ev.y, ev.z, ev.w};
#pragma unroll
    for (int j = 0; j < 4; j++) {
        float x = xs[j], e = es[j];
        float p = as[j] * acs[j];
        float c = cs[j] * acs[j];
        float d = ds[j];
        s[0] += e * p * x;  s[1] += e * x;
        s[2] += e * c * x;  s[3] += e * d * x;
        s[4] += p * x;      s[5] += x;
        s[6] += c * x;      s[7] += d * x;
    }
}

// ---------------------------------------------------------------------------
// Fused GEMV: cp.async stage pipeline (RPS rows = 32 KB per stage, NBUF deep),
// x in registers, thread t owns f4-columns {t, t+512, ...}. Per-stage shfl
// reduce (paired butterfly when RPS=2); no block barrier on the data path.
// ---------------------------------------------------------------------------
template <int NCOL4, int NROWS_OUT, bool TANH_IN, bool TANH_OUT, int NBUF, int RPS>
__device__ __forceinline__ void gemv_fused(
    const float* __restrict__ W,
    const float* __restrict__ xin_src,
    const float* __restrict__ act_pre,
    const float* __restrict__ a_pre,
    const float* __restrict__ c_pre,
    const float* __restrict__ d_pre,
    const float* __restrict__ e_pre,
    const float* __restrict__ act_post,
    const float* __restrict__ b_post,
    const float* __restrict__ c_post,
    const float* __restrict__ d_post,
    const float* __restrict__ e_post,
    float* __restrict__ out)
{
    constexpr int F4PT = NCOL4 / BLK;        // float4 per thread per row (2 or 4)
    constexpr int STAGE_F4 = RPS * NCOL4;    // float4 per stage buffer
    constexpr int FLUSH = 8 / RPS;           // stages per 8-row output group

    extern __shared__ float4 dynbuf[];       // NBUF * STAGE_F4 float4 (96 KB)
    __shared__ float sh[8][16];
    __shared__ float s_sums[8];
    __shared__ float s_heb[32];
    __shared__ float s_part[2][8][16];

    int tid = threadIdx.x;
    int lane = tid & 31;
    int warp = tid >> 5;

    int r_lo = (int)(((long long)blockIdx.x * NROWS_OUT) / NBLK);
    int r_hi = (int)(((long long)(blockIdx.x + 1) * NROWS_OUT) / NBLK);
    int nrows = r_hi - r_lo;
    int nstages = (nrows + RPS - 1) / RPS;

    const float4* Wb = reinterpret_cast<const float4*>(W) + (size_t)r_lo * NCOL4;
    uint32_t sbase = smem_u32(dynbuf);

    auto issue_stage = [&](int s) {
        if (s < nstages) {
            uint32_t dbase = sbase + (uint32_t)((s % NBUF) * STAGE_F4) * 16u;
#pragma unroll
            for (int k = 0; k < RPS; k++) {
                int rr = s * RPS + k;
                if (rr >= nrows) rr = nrows - 1;    // clamp (loads only)
                const float4* src = Wb + (size_t)rr * NCOL4 + tid;
#pragma unroll
                for (int j = 0; j < F4PT; j++)
                    cp_async16(dbase + (uint32_t)(k * NCOL4 + j * BLK + tid) * 16u,
                               src + j * BLK);
            }
        }
        CP_COMMIT();
    };

    // Kick off DRAM immediately: prefetch first NBUF stages.
#pragma unroll
    for (int s = 0; s < NBUF; s++) issue_stage(s);

    // x into registers (+tanh), Hebbian pre-side sums (overlaps prefetch).
    float4 xr[F4PT];
    {
        float s[8] = {0.f, 0.f, 0.f, 0.f, 0.f, 0.f, 0.f, 0.f};
#pragma unroll
        for (int j = 0; j < F4PT; j++) {
            int i = tid + j * BLK;
            float4 xv = reinterpret_cast<const float4*>(xin_src)[i];
            if (TANH_IN)
                xv = make_float4(tanhf(xv.x), tanhf(xv.y), tanhf(xv.z), tanhf(xv.w));
            xr[j] = xv;
            float4 actv = reinterpret_cast<const float4*>(act_pre)[i];
            float4 av   = reinterpret_cast<const float4*>(a_pre)[i];
            float4 cv   = reinterpret_cast<const float4*>(c_pre)[i];
            float4 dv   = reinterpret_cast<const float4*>(d_pre)[i];
            float4 ev   = reinterpret_cast<const float4*>(e_pre)[i];
            heb_partial4(s, xv, actv, av, cv, dv, ev);
        }
        block_reduce8(s, sh, s_sums);
    }
    __syncthreads();
    if (tid < nrows) {
        s_heb[tid] = heb_row_val(r_lo + tid, act_post, b_post, c_post, d_post,
                                 e_post, s_sums);
    }
    __syncthreads();

    int par = 0;
    for (int s = 0; s < nstages; s++) {
        CP_WAIT(NBUF - 1);

        const float4* buf = dynbuf + (size_t)(s % NBUF) * STAGE_F4;
        float4 wv[RPS][F4PT];
#pragma unroll
        for (int k = 0; k < RPS; k++)
#pragma unroll
            for (int j = 0; j < F4PT; j++)
                wv[k][j] = buf[k * NCOL4 + j * BLK + tid];

        // Refill this slot for stage s+NBUF (regs already hold the data).
        issue_stage(s + NBUF);

        float acc[RPS];
#pragma unroll
        for (int k = 0; k < RPS; k++) {
            float a = 0.f;
#pragma unroll
            for (int j = 0; j < F4PT; j++) {
                a = fmaf(wv[k][j].x, xr[j].x, a);
                a = fmaf(wv[k][j].y, xr[j].y, a);
                a = fmaf(wv[k][j].z, xr[j].z, a);
                a = fmaf(wv[k][j].w, xr[j].w, a);
            }
            acc[k] = a;
        }

        int rbase = s * RPS;
        if (RPS == 2) {
            // Paired butterfly: lanes<16 reduce acc[0], lanes>=16 reduce acc[1].
            float h0 = __shfl_xor_sync(0xffffffffu, acc[0], 16);
            float h1 = __shfl_xor_sync(0xffffffffu, acc[1], 16);
            float v = (lane < 16) ? (acc[0] + h0) : (acc[1] + h1);
#pragma unroll
            for (int o = 8; o > 0; o >>= 1) v += __shfl_xor_sync(0xffffffffu, v, o);
            if (lane == 0)  s_part[par][rbase & 7][warp] = v;
            if (lane == 16) s_part[par][(rbase + 1) & 7][warp] = v;
        } else {
            float v = warp_sum(acc[0]);
            if (lane == 0) s_part[par][rbase & 7][warp] = v;
        }

        if (((s + 1) % FLUSH == 0) || s == nstages - 1) {
            __syncthreads();
            if (tid < 256) {
                int rr = (rbase & ~7) + warp;   // warp = 0..7 here
                if (rr < nrows) {
                    float v = (lane < 16) ? s_part[par][warp][lane] : 0.f;
                    v = warp_sum(v);
                    if (lane == 0) {
                        float y = v + s_heb[rr];
                        out[r_lo + rr] = TANH_OUT ? tanhf(y) : y;
                    }
                }
            }
            par ^= 1;
        }
    }
}

// ---------------------------------------------------------------------------
__global__ void __launch_bounds__(BLK, 2) k_gemv0(
    const float* __restrict__ W0,
    const float* __restrict__ inputs,
    const float* __restrict__ act0,
    const float* __restrict__ a0,
    const float* __restrict__ c0,
    const float* __restrict__ d0,
    const float* __restrict__ e0,
    const float* __restrict__ act1,
    const float* __restrict__ b1,
    const float* __restrict__ c1,
    const float* __restrict__ d1,
    const float* __restrict__ e1)
{
    gemv_fused<N0 / 4, N1, true, true, 3, 2>(
        W0, inputs, act0, a0, c0, d0, e0,
        act1, b1, c1, d1, e1, g_x1);
}

__global__ void __launch_bounds__(BLK, 2) k_gemv1(
    const float* __restrict__ W1,
    const float* __restrict__ act1,
    const float* __restrict__ a1,
    const float* __restrict__ c1,
    const float* __restrict__ d1,
    const float* __restrict__ e1,
    const float* __restrict__ act2,
    const float* __restrict__ b2,
    const float* __restrict__ c2,
    const float* __restrict__ d2,
    const float* __restrict__ e2,
    float* __restrict__ out)
{
    gemv_fused<N1 / 4, N2, false, false, 3, 1>(
        W1, g_x1, act1, a1, c1, d1, e1,
        act2, b2, c2, d2, e2, out);
}

// ---------------------------------------------------------------------------
extern "C" void kernel_launch(void* const* d_in, const int* in_sizes, int n_in,
                              void* d_out, int out_size)
{
    const float* inputs = (const float*)d_in[0];
    const float* act0   = (const float*)d_in[1];
    const float* act1   = (const float*)d_in[2];
    const float* act2   = (const float*)d_in[3];
    const float* W0     = (const float*)d_in[4];
    const float* W1     = (const float*)d_in[5];
    const float* a0     = (const float*)d_in[6];
    const float* c0     = (const float*)d_in[7];
    const float* d0     = (const float*)d_in[8];
    const float* e0     = (const float*)d_in[9];
    const float* a1     = (const float*)d_in[10];
    const float* b1     = (const float*)d_in[11];
    const float* c1     = (const float*)d_in[12];
    const float* d1     = (const float*)d_in[13];
    const float* e1     = (const float*)d_in[14];
    const float* b2     = (const float*)d_in[15];
    const float* c2     = (const float*)d_in[16];
    const float* d2     = (const float*)d_in[17];
    const float* e2     = (const float*)d_in[18];
    float* out = (float*)d_out;

    // 3 stages * 32 KB = 96 KB dynamic smem for both kernels.
    const int SMEM_DYN = 3 * 2 * (N0 / 4) * (int)sizeof(float4);
    cudaFuncSetAttribute(k_gemv0, cudaFuncAttributeMaxDynamicSharedMemorySize, SMEM_DYN);
    cudaFuncSetAttribute(k_gemv1, cudaFuncAttributeMaxDynamicSharedMemorySize, SMEM_DYN);

    k_gemv0<<<NBLK, BLK, SMEM_DYN>>>(W0, inputs, act0, a0, c0, d0, e0,
                                     act1, b1, c1, d1, e1);
    k_gemv1<<<NBLK, BLK, SMEM_DYN>>>(W1, act1, a1, c1, d1, e1,
                                     act2, b2, c2, d2, e2, out);
}

// round 11
// speedup vs baseline: 1.1787x; 1.1038x over previous
#include <cuda_runtime.h>
#include <cstdint>

#define N0 4096
#define N1 8192
#define N2 4096
#define NBLK 296           // 2 CTAs per SM
#define BLK 512

// Scratch (allocation-free: __device__ global)
__device__ __align__(16) float g_x1[N1];

__device__ __forceinline__ float warp_sum(float v) {
#pragma unroll
    for (int o = 16; o > 0; o >>= 1) v += __shfl_xor_sync(0xffffffffu, v, o);
    return v;
}

__device__ __forceinline__ uint32_t smem_u32(const void* p) {
    return (uint32_t)__cvta_generic_to_shared(p);
}
__device__ __forceinline__ void cp_async16(uint32_t dst, const void* src) {
    asm volatile("cp.async.cg.shared.global [%0], [%1], 16;" :: "r"(dst), "l"(src));
}
#define CP_COMMIT() asm volatile("cp.async.commit_group;" ::: "memory")
#define CP_WAIT(n)  asm volatile("cp.async.wait_group %0;" :: "n"(n) : "memory")

// Block-wide reduction of 8 partial sums (512 threads / 16 warps). Deterministic.
__device__ __forceinline__ void block_reduce8(float s[8], float (*sh)[16], float* s_sums)
{
    int tid = threadIdx.x;
    int w = tid >> 5, l = tid & 31;
#pragma unroll
    for (int k = 0; k < 8; k++) s[k] = warp_sum(s[k]);
    if (l == 0) {
#pragma unroll
        for (int k = 0; k < 8; k++) sh[k][w] = s[k];
    }
    __syncthreads();
    if (tid < 256) {
        int k = tid >> 5, ln = tid & 31;
        float v = (ln < 16) ? sh[k][ln] : 0.f;
        v = warp_sum(v);
        if (ln == 0) s_sums[k] = v;
    }
}

__device__ __forceinline__ float heb_row_val(
    int row,
    const float* __restrict__ act_post,
    const float* __restrict__ b_post,
    const float* __restrict__ c_post,
    const float* __restrict__ d_post,
    const float* __restrict__ e_post,
    const float* __restrict__ sums)
{
    float P = b_post[row] * act_post[row];
    float C = c_post[row] * act_post[row];
    float D = d_post[row];
    float E = e_post[row];
    return 0.5f * (sums[0] + P * sums[1] + C * sums[2] + D * sums[3]
          + E * (sums[4] + P * sums[5] + C * sums[6] + D * sums[7]));
}

__device__ __forceinline__ void heb_partial4(
    float s[8], float4 xv, float4 actv, float4 av, float4 cv, float4 dv, float4 ev)
{
    float xs[4]  = {xv.x, xv.y, xv.z, xv.w};
    float acs[4] = {actv.x, actv.y, actv.z, actv.w};
    float as[4]  = {av.x, av.y, av.z, av.w};
    float cs[4]  = {cv.x, cv.y, cv.z, cv.w};
    float ds[4]  = {dv.x, dv.y, dv.z, dv.w};
    float es[4]  = {ev.x, ev.y, ev.z, ev.w};
#pragma unroll
    for (int j = 0; j < 4; j++) {
        float x = xs[j], e = es[j];
        float p = as[j] * acs[j];
        float c = cs[j] * acs[j];
        float d = ds[j];
        s[0] += e * p * x;  s[1] += e * x;
        s[2] += e * c * x;  s[3] += e * d * x;
        s[4] += p * x;      s[5] += x;
        s[6] += c * x;      s[7] += d * x;
    }
}

// ===========================================================================
// k_gemv0: W0[8192 x 4096] @ tanh(inputs), +hebbian, tanh -> g_x1.
// NBUF=6 ring of 16 KB rows, TWO rows retired per CP_WAIT (paired butterfly).
// ===========================================================================
__global__ void __launch_bounds__(BLK, 2) k_gemv0(
    const float* __restrict__ W0,
    const float* __restrict__ inputs,
    const float* __restrict__ act0,
    const float* __restrict__ a0,
    const float* __restrict__ c0,
    const float* __restrict__ d0,
    const float* __restrict__ e0,
    const float* __restrict__ act1,
    const float* __restrict__ b1,
    const float* __restrict__ c1,
    const float* __restrict__ d1,
    const float* __restrict__ e1)
{
    constexpr int NCOL4 = N0 / 4;     // 1024
    constexpr int NBUF = 6;

    extern __shared__ float4 dynbuf[];    // 6 * 1024 float4 = 96 KB
    __shared__ float sh[8][16];
    __shared__ float s_sums[8];
    __shared__ float s_heb[32];
    __shared__ float s_part[2][8][16];

    int tid = threadIdx.x;
    int lane = tid & 31;
    int warp = tid >> 5;

    int r_lo = (int)(((long long)blockIdx.x * N1) / NBLK);
    int r_hi = (int)(((long long)(blockIdx.x + 1) * N1) / NBLK);
    int nrows = r_hi - r_lo;

    const float4* Wb = reinterpret_cast<const float4*>(W0) + (size_t)r_lo * NCOL4;
    uint32_t sbase = smem_u32(dynbuf);

    // Prefetch first NBUF rows (1 commit group per row).
#pragma unroll
    for (int r = 0; r < NBUF; r++) {
        if (r < nrows) {
            cp_async16(sbase + (uint32_t)(r * NCOL4 + tid) * 16u,
                       Wb + (size_t)r * NCOL4 + tid);
            cp_async16(sbase + (uint32_t)(r * NCOL4 + tid + BLK) * 16u,
                       Wb + (size_t)r * NCOL4 + tid + BLK);
        }
        CP_COMMIT();
    }

    // x into registers (+tanh), Hebbian pre-side sums (overlaps prefetch).
    float4 xr[2];
    {
        float s[8] = {0.f, 0.f, 0.f, 0.f, 0.f, 0.f, 0.f, 0.f};
#pragma unroll
        for (int j = 0; j < 2; j++) {
            int i = tid + j * BLK;
            float4 xv = reinterpret_cast<const float4*>(inputs)[i];
            xv = make_float4(tanhf(xv.x), tanhf(xv.y), tanhf(xv.z), tanhf(xv.w));
            xr[j] = xv;
            float4 actv = reinterpret_cast<const float4*>(act0)[i];
            float4 av   = reinterpret_cast<const float4*>(a0)[i];
            float4 cv   = reinterpret_cast<const float4*>(c0)[i];
            float4 dv   = reinterpret_cast<const float4*>(d0)[i];
            float4 ev   = reinterpret_cast<const float4*>(e0)[i];
            heb_partial4(s, xv, actv, av, cv, dv, ev);
        }
        block_reduce8(s, sh, s_sums);
    }
    __syncthreads();
    if (tid < nrows) {
        s_heb[tid] = heb_row_val(r_lo + tid, act1, b1, c1, d1, e1, s_sums);
    }
    __syncthreads();

    int rdSlot = 0;
    int wrSlot = 0;
    const float4* gsrc = Wb + (size_t)NBUF * NCOL4 + tid;

    int par = 0;
    int r = 0;
    for (; r + 1 < nrows; r += 2) {
        CP_WAIT(4);                       // rows r and r+1 complete

        const float4* bA = dynbuf + (size_t)rdSlot * NCOL4;
        rdSlot = (rdSlot + 1 == NBUF) ? 0 : rdSlot + 1;
        const float4* bB = dynbuf + (size_t)rdSlot * NCOL4;
        rdSlot = (rdSlot + 1 == NBUF) ? 0 : rdSlot + 1;

        float4 wA0 = bA[tid], wA1 = bA[tid + BLK];
        float4 wB0 = bB[tid], wB1 = bB[tid + BLK];

        float accA = 0.f, accB = 0.f;
        accA = fmaf(wA0.x, xr[0].x, accA);
        accA = fmaf(wA0.y, xr[0].y, accA);
        accA = fmaf(wA0.z, xr[0].z, accA);
        accA = fmaf(wA0.w, xr[0].w, accA);
        accA = fmaf(wA1.x, xr[1].x, accA);
        accA = fmaf(wA1.y, xr[1].y, accA);
        accA = fmaf(wA1.z, xr[1].z, accA);
        accA = fmaf(wA1.w, xr[1].w, accA);
        accB = fmaf(wB0.x, xr[0].x, accB);
        accB = fmaf(wB0.y, xr[0].y, accB);
        accB = fmaf(wB0.z, xr[0].z, accB);
        accB = fmaf(wB0.w, xr[0].w, accB);
        accB = fmaf(wB1.x, xr[1].x, accB);
        accB = fmaf(wB1.y, xr[1].y, accB);
        accB = fmaf(wB1.z, xr[1].z, accB);
        accB = fmaf(wB1.w, xr[1].w, accB);

        // Refill the two freed slots (rows r+6, r+7); 1 commit each.
        if (r + NBUF < nrows) {
            uint32_t wb = sbase + (uint32_t)(wrSlot * NCOL4 + tid) * 16u;
            cp_async16(wb, gsrc);
            cp_async16(wb + (uint32_t)BLK * 16u, gsrc + BLK);
        }
        wrSlot = (wrSlot + 1 == NBUF) ? 0 : wrSlot + 1;
        gsrc += NCOL4;
        CP_COMMIT();
        if (r + NBUF + 1 < nrows) {
            uint32_t wb = sbase + (uint32_t)(wrSlot * NCOL4 + tid) * 16u;
            cp_async16(wb, gsrc);
            cp_async16(wb + (uint32_t)BLK * 16u, gsrc + BLK);
        }
        wrSlot = (wrSlot + 1 == NBUF) ? 0 : wrSlot + 1;
        gsrc += NCOL4;
        CP_COMMIT();

        // Paired butterfly: lanes<16 finish row A, lanes>=16 finish row B.
        float hA = __shfl_xor_sync(0xffffffffu, accA, 16);
        float hB = __shfl_xor_sync(0xffffffffu, accB, 16);
        float v = (lane < 16) ? (accA + hA) : (accB + hB);
#pragma unroll
        for (int o = 8; o > 0; o >>= 1) v += __shfl_xor_sync(0xffffffffu, v, o);
        if (lane == 0)  s_part[par][r & 7][warp] = v;
        if (lane == 16) s_part[par][(r + 1) & 7][warp] = v;

        int done = r + 1;
        if ((done & 7) == 7 || done == nrows - 1) {
            __syncthreads();
            if (tid < 256) {
                int rr = (done & ~7) + warp;   // warp = 0..7 here
                if (rr < nrows) {
                    float vv = (lane < 16) ? s_part[par][warp][lane] : 0.f;
                    vv = warp_sum(vv);
                    if (lane == 0)
                        g_x1[r_lo + rr] = tanhf(vv + s_heb[rr]);
                }
            }
            par ^= 1;
        }
    }

    // Odd tail row.
    if (r < nrows) {
        CP_WAIT(0);
        const float4* bA = dynbuf + (size_t)rdSlot * NCOL4;
        float4 wA0 = bA[tid], wA1 = bA[tid + BLK];
        float acc = 0.f;
        acc = fmaf(wA0.x, xr[0].x, acc);
        acc = fmaf(wA0.y, xr[0].y, acc);
        acc = fmaf(wA0.z, xr[0].z, acc);
        acc = fmaf(wA0.w, xr[0].w, acc);
        acc = fmaf(wA1.x, xr[1].x, acc);
        acc = fmaf(wA1.y, xr[1].y, acc);
        acc = fmaf(wA1.z, xr[1].z, acc);
        acc = fmaf(wA1.w, xr[1].w, acc);
        float v = warp_sum(acc);
        if (lane == 0) s_part[par][r & 7][warp] = v;
        __syncthreads();
        if (tid < 256) {
            int rr = (r & ~7) + warp;
            if (rr < nrows) {
                float vv = (lane < 16) ? s_part[par][warp][lane] : 0.f;
                vv = warp_sum(vv);
                if (lane == 0)
                    g_x1[r_lo + rr] = tanhf(vv + s_heb[rr]);
            }
        }
    }
}

// ===========================================================================
// k_gemv1: W1[4096 x 8192] @ g_x1, +hebbian -> out.  (R8 verbatim)
// ===========================================================================
__global__ void __launch_bounds__(BLK, 2) k_gemv1(
    const float* __restrict__ W1,
    const float* __restrict__ act1,
    const float* __restrict__ a1,
    const float* __restrict__ c1,
    const float* __restrict__ d1,
    const float* __restrict__ e1,
    const float* __restrict__ act2,
    const float* __restrict__ b2,
    const float* __restrict__ c2,
    const float* __restrict__ d2,
    const float* __restrict__ e2,
    float* __restrict__ out)
{
    constexpr int NCOL4 = N1 / 4;   // 2048
    constexpr int NBUF = 3;
    constexpr int F4PT = 4;

    extern __shared__ float4 dynbuf[];    // 3 * 2048 float4 = 96 KB
    __shared__ float sh[8][16];
    __shared__ float s_sums[8];
    __shared__ float s_heb[32];
    __shared__ float s_part[2][8][16];

    int tid = threadIdx.x;
    int lane = tid & 31;
    int warp = tid >> 5;

    int r_lo = (int)(((long long)blockIdx.x * N2) / NBLK);
    int r_hi = (int)(((long long)(blockIdx.x + 1) * N2) / NBLK);
    int nrows = r_hi - r_lo;

    const float4* Wb = reinterpret_cast<const float4*>(W1) + (size_t)r_lo * NCOL4;
    uint32_t sbase = smem_u32(dynbuf);

#pragma unroll
    for (int r = 0; r < NBUF; r++) {
        if (r < nrows) {
#pragma unroll
            for (int j = 0; j < F4PT; j++) {
                int col = tid + j * BLK;
                cp_async16(sbase + (uint32_t)(r * NCOL4 + col) * 16u,
                           Wb + (size_t)r * NCOL4 + col);
            }
        }
        CP_COMMIT();
    }

    float4 xr[F4PT];
    {
        float s[8] = {0.f, 0.f, 0.f, 0.f, 0.f, 0.f, 0.f, 0.f};
#pragma unroll
        for (int j = 0; j < F4PT; j++) {
            int i = tid + j * BLK;
            float4 xv = reinterpret_cast<const float4*>(g_x1)[i];
            xr[j] = xv;
            float4 actv = reinterpret_cast<const float4*>(act1)[i];
            float4 av   = reinterpret_cast<const float4*>(a1)[i];
            float4 cv   = reinterpret_cast<const float4*>(c1)[i];
            float4 dv   = reinterpret_cast<const float4*>(d1)[i];
            float4 ev   = reinterpret_cast<const float4*>(e1)[i];
            heb_partial4(s, xv, actv, av, cv, dv, ev);
        }
        block_reduce8(s, sh, s_sums);
    }
    __syncthreads();
    if (tid < nrows) {
        s_heb[tid] = heb_row_val(r_lo + tid, act2, b2, c2, d2, e2, s_sums);
    }
    __syncthreads();

    int rdSlot = 0;
    int wrSlot = 0;
    const float4* gsrc = Wb + (size_t)NBUF * NCOL4 + tid;

    int par = 0;
    for (int r = 0; r < nrows; r++) {
        CP_WAIT(NBUF - 1);

        const float4* buf = dynbuf + (size_t)rdSlot * NCOL4;
        float4 wv[F4PT];
#pragma unroll
        for (int j = 0; j < F4PT; j++) wv[j] = buf[tid + j * BLK];
        rdSlot = (rdSlot + 1 == NBUF) ? 0 : rdSlot + 1;

        float acc = 0.f;
#pragma unroll
        for (int j = 0; j < F4PT; j++) {
            acc = fmaf(wv[j].x, xr[j].x, acc);
            acc = fmaf(wv[j].y, xr[j].y, acc);
            acc = fmaf(wv[j].z, xr[j].z, acc);
            acc = fmaf(wv[j].w, xr[j].w, acc);
        }
        float p = warp_sum(acc);
        if (lane == 0) s_part[par][r & 7][warp] = p;

        if (r + NBUF < nrows) {
            uint32_t wbase = sbase + (uint32_t)(wrSlot * NCOL4 + tid) * 16u;
#pragma unroll
            for (int j = 0; j < F4PT; j++)
                cp_async16(wbase + (uint32_t)(j * BLK) * 16u, gsrc + j * BLK);
        }
        wrSlot = (wrSlot + 1 == NBUF) ? 0 : wrSlot + 1;
        gsrc += NCOL4;
        CP_COMMIT();

        if ((r & 7) == 7 || r == nrows - 1) {
            __syncthreads();
            if (tid < 256) {
                int rr = (r & ~7) + warp;
                if (rr < nrows) {
                    float v = (lane < 16) ? s_part[par][warp][lane] : 0.f;
                    v = warp_sum(v);
                    if (lane == 0) {
                        out[r_lo + rr] = v + s_heb[rr];
                    }
                }
            }
            par ^= 1;
        }
    }
}

// ---------------------------------------------------------------------------
extern "C" void kernel_launch(void* const* d_in, const int* in_sizes, int n_in,
                              void* d_out, int out_size)
{
    const float* inputs = (const float*)d_in[0];
    const float* act0   = (const float*)d_in[1];
    const float* act1   = (const float*)d_in[2];
    const float* act2   = (const float*)d_in[3];
    const float* W0     = (const float*)d_in[4];
    const float* W1     = (const float*)d_in[5];
    const float* a0     = (const float*)d_in[6];
    const float* c0     = (const float*)d_in[7];
    const float* d0     = (const float*)d_in[8];
    const float* e0     = (const float*)d_in[9];
    const float* a1     = (const float*)d_in[10];
    const float* b1     = (const float*)d_in[11];
    const float* c1     = (const float*)d_in[12];
    const float* d1     = (const float*)d_in[13];
    const float* e1     = (const float*)d_in[14];
    const float* b2     = (const float*)d_in[15];
    const float* c2     = (const float*)d_in[16];
    const float* d2     = (const float*)d_in[17];
    const float* e2     = (const float*)d_in[18];
    float* out = (float*)d_out;

    // 96 KB dynamic smem for both kernels.
    const int SMEM_DYN = 6 * (N0 / 4) * (int)sizeof(float4);
    cudaFuncSetAttribute(k_gemv0, cudaFuncAttributeMaxDynamicSharedMemorySize, SMEM_DYN);
    cudaFuncSetAttribute(k_gemv1, cudaFuncAttributeMaxDynamicSharedMemorySize, SMEM_DYN);

    k_gemv0<<<NBLK, BLK, SMEM_DYN>>>(W0, inputs, act0, a0, c0, d0, e0,
                                     act1, b1, c1, d1, e1);
    k_gemv1<<<NBLK, BLK, SMEM_DYN>>>(W1, act1, a1, c1, d1, e1,
                                     act2, b2, c2, d2, e2, out);
}